// round 5
// baseline (speedup 1.0000x reference)
#include <cuda_runtime.h>
#include <cstdint>

#define BB 128
#define SS 512
#define EE 512
#define HH 1024
#define TOK (BB*SS)
#define NCTA 128

// Scratch (allocation-free rule: __device__ globals)
__device__ float g_pre[(size_t)TOK * HH];   // [s*B + b][h], fp32
__device__ float g_h[2][BB * HH];           // ping-pong hidden state
__device__ unsigned g_cnt;                  // monotonic barrier counter

__device__ __forceinline__ unsigned f2tf(float f){
  unsigned u; asm("cvt.rna.tf32.f32 %0, %1;" : "=r"(u) : "f"(f)); return u;
}

__device__ __forceinline__ void mma8(float c[4], unsigned a0,unsigned a1,unsigned a2,unsigned a3,
                                     unsigned b0,unsigned b1){
  asm volatile("mma.sync.aligned.m16n8k8.row.col.f32.tf32.tf32.f32 "
    "{%0,%1,%2,%3}, {%4,%5,%6,%7}, {%8,%9}, {%0,%1,%2,%3};"
    : "+f"(c[0]),"+f"(c[1]),"+f"(c[2]),"+f"(c[3])
    : "r"(a0),"r"(a1),"r"(a2),"r"(a3),"r"(b0),"r"(b1));
}

__global__ void k_init(){
  int i = blockIdx.x*blockDim.x + threadIdx.x;
  if (i < BB*HH) g_h[0][i] = 0.f;
  if (i == 0){ g_cnt = 0u; }
}

// pre[s*B+b][h] = dot(emb[x[b][s]], W[h]) + Wb[h]   (M=65536, N=1024, K=512)
__global__ __launch_bounds__(256) void k_pre(const int* __restrict__ x, const float* __restrict__ emb,
                                             const float* __restrict__ Ww, const float* __restrict__ Wb){
  __shared__ unsigned As[64][33];
  __shared__ unsigned Bsm[64][33];
  __shared__ const float* rowp[64];
  const int tid = threadIdx.x;
  const int m0 = blockIdx.y*64, n0 = blockIdx.x*64;
  if (tid < 64){
    int tok = m0 + tid;
    int b = tok & (BB-1), s = tok >> 7;
    rowp[tid] = emb + (size_t)x[b*SS + s]*EE;
  }
  __syncthreads();
  const int lane = tid & 31, wid = tid >> 5;
  const int wm = wid >> 1, wn = wid & 1;
  const int gr = lane >> 2, gq = lane & 3;
  float acc[4][4];
  #pragma unroll
  for (int i=0;i<4;i++){ acc[i][0]=0.f; acc[i][1]=0.f; acc[i][2]=0.f; acc[i][3]=0.f; }

  for (int kt = 0; kt < EE/32; ++kt){
    const int k0 = kt*32;
    #pragma unroll
    for (int it=0; it<2; ++it){
      int id = tid + it*256;
      int r = id >> 3, c4 = (id & 7)*4;
      float4 v = *(const float4*)(rowp[r] + k0 + c4);
      As[r][c4+0]=f2tf(v.x); As[r][c4+1]=f2tf(v.y); As[r][c4+2]=f2tf(v.z); As[r][c4+3]=f2tf(v.w);
      float4 w = *(const float4*)(Ww + (size_t)(n0+r)*EE + k0 + c4);
      Bsm[r][c4+0]=f2tf(w.x); Bsm[r][c4+1]=f2tf(w.y); Bsm[r][c4+2]=f2tf(w.z); Bsm[r][c4+3]=f2tf(w.w);
    }
    __syncthreads();
    #pragma unroll
    for (int kk=0; kk<4; ++kk){
      unsigned a0 = As[wm*16+gr  ][kk*8+gq];
      unsigned a1 = As[wm*16+gr+8][kk*8+gq];
      unsigned a2 = As[wm*16+gr  ][kk*8+gq+4];
      unsigned a3 = As[wm*16+gr+8][kk*8+gq+4];
      #pragma unroll
      for (int nf=0; nf<4; ++nf){
        int nr = wn*32 + nf*8 + gr;
        mma8(acc[nf], a0,a1,a2,a3, Bsm[nr][kk*8+gq], Bsm[nr][kk*8+gq+4]);
      }
    }
    __syncthreads();
  }
  #pragma unroll
  for (int nf=0; nf<4; ++nf){
    int nc = n0 + wn*32 + nf*8 + 2*gq;
    int mr = m0 + wm*16 + gr;
    float wb0 = Wb[nc], wb1 = Wb[nc+1];
    g_pre[(size_t)mr*HH + nc]        = acc[nf][0] + wb0;
    g_pre[(size_t)mr*HH + nc + 1]    = acc[nf][1] + wb1;
    g_pre[(size_t)(mr+8)*HH + nc]    = acc[nf][2] + wb0;
    g_pre[(size_t)(mr+8)*HH + nc+1]  = acc[nf][3] + wb1;
  }
}

// ---------------- persistent recurrence kernel ----------------
// 128 CTAs = 4 (M, 32 rows) x 32 (N, 32 cols), 256 threads, 8 warps.
// Per chunk (128 K): all threads convert h chunk -> hi/lo tf32 fragments in SMEM once,
// then all warps run a pure LDS+MMA loop with split accumulators.
// SMEM words: Bp [0,32768) packed U; Apack [32768,40960) hi(4096)+lo(4096);
//             stage [40960,49408) 2 x 32 x 132 raw fp32.
#define SM_BP    0
#define SM_APACK 32768
#define SM_STAGE 40960
#define STAGE_WORDS (32*132)
#define SMEM_WORDS (40960 + 2*STAGE_WORDS)

__device__ __forceinline__ void cpa16(unsigned* dst_sm, const float* src){
  uint32_t sa = (uint32_t)__cvta_generic_to_shared(dst_sm);
  asm volatile("cp.async.cg.shared.global [%0], [%1], 16;" :: "r"(sa), "l"(src));
}

__global__ __launch_bounds__(256, 1) void k_scan(const float* __restrict__ U, const float* __restrict__ Ub){
  extern __shared__ unsigned smw[];
  const int tid = threadIdx.x, lane = tid & 31, wid = tid >> 5;
  const int gr = lane >> 2, gq = lane & 3;
  const int wm = wid & 1, wn = wid >> 1;
  const int m0 = blockIdx.y*32, n0 = blockIdx.x*32;

  // ---- pack U slice (rows n0..n0+31 of U, full K) into tf32 B-fragments ----
  for (int e = tid; e < 32*HH; e += 256){
    int n = e >> 10, k = e & (HH-1);
    float v = U[(size_t)(n0+n)*HH + k];
    int kg = k >> 3, kk = k & 7;
    int w = ((kg*4 + (n>>3))*32 + (n&7)*4 + (kk&3))*2 + (kk>>2);
    smw[SM_BP + w] = f2tf(v);
  }
  const int nc = n0 + wn*8 + 2*gq;
  const int mr = m0 + wm*16 + gr;
  const float ub0 = Ub[nc], ub1 = Ub[nc+1];
  __syncthreads();

  for (int t = 0; t < SS; ++t){
    const float* __restrict__ hold = g_h[t & 1];
    float* __restrict__ hnew = g_h[(t & 1) ^ 1];
    const float* __restrict__ pre = g_pre + (size_t)t*BB*HH;

    const float pv0 = pre[(size_t)mr*HH + nc];
    const float pv1 = pre[(size_t)mr*HH + nc + 1];
    const float pv2 = pre[(size_t)(mr+8)*HH + nc];
    const float pv3 = pre[(size_t)(mr+8)*HH + nc + 1];
    float accH[4] = {0.f,0.f,0.f,0.f};
    float accL[4] = {0.f,0.f,0.f,0.f};

    // prefetch chunk 0 (32 rows x 128 floats) into stage buf 0
    #pragma unroll
    for (int i=0;i<4;++i){
      int idx = tid + i*256; int r = idx >> 5, j = idx & 31;
      cpa16(smw + SM_STAGE + r*132 + j*4, hold + (size_t)(m0+r)*HH + j*4);
    }
    asm volatile("cp.async.commit_group;");

    #pragma unroll 1
    for (int c = 0; c < 8; ++c){
      if (c < 7){
        int buf = (c+1) & 1;
        #pragma unroll
        for (int i=0;i<4;++i){
          int idx = tid + i*256; int r = idx >> 5, j = idx & 31;
          cpa16(smw + SM_STAGE + buf*STAGE_WORDS + r*132 + j*4,
                hold + (size_t)(m0+r)*HH + (c+1)*128 + j*4);
        }
        asm volatile("cp.async.commit_group;");
        asm volatile("cp.async.wait_group 1;" ::: "memory");
      } else {
        asm volatile("cp.async.wait_group 0;" ::: "memory");
      }
      __syncthreads();   // stage[c&1] ready; Apack free (prev chunk's mma done)

      // ---- cooperative convert: chunk -> hi/lo packed fragments (once) ----
      {
        const float* stg = (const float*)(smw + SM_STAGE + (c&1)*STAGE_WORDS);
        #pragma unroll
        for (int j = 0; j < 4; ++j){
          int p = wid + j*8;             // p = kb*2 + wmj, covers 0..31
          int kb = p >> 1, wmj = p & 1;
          const float* base = stg + (wmj*16 + gr)*132 + kb*8 + gq;
          float v0 = base[0];
          float v1 = base[8*132];
          float v2 = base[4];
          float v3 = base[8*132 + 4];
          unsigned h0=f2tf(v0), h1=f2tf(v1), h2=f2tf(v2), h3=f2tf(v3);
          unsigned l0=f2tf(v0-__uint_as_float(h0));
          unsigned l1=f2tf(v1-__uint_as_float(h1));
          unsigned l2=f2tf(v2-__uint_as_float(h2));
          unsigned l3=f2tf(v3-__uint_as_float(h3));
          unsigned off = (unsigned)(p*32 + lane)*4;
          *(uint4*)(smw + SM_APACK + off)        = make_uint4(h0,h1,h2,h3);
          *(uint4*)(smw + SM_APACK + 4096 + off) = make_uint4(l0,l1,l2,l3);
        }
      }
      __syncthreads();   // Apack ready

      // ---- pure LDS + MMA, split accumulators ----
      {
        const unsigned* ap = smw + SM_APACK;
        const unsigned* bp = smw + SM_BP + c*4096 + (wn*32 + lane)*2;
        #pragma unroll
        for (int kb = 0; kb < 16; ++kb){
          unsigned off = (unsigned)((kb*2 + wm)*32 + lane)*4;
          uint4 ah = *(const uint4*)(ap + off);
          uint4 al = *(const uint4*)(ap + 4096 + off);
          uint2 bb = *(const uint2*)(bp + kb*256);
          mma8(accH, ah.x,ah.y,ah.z,ah.w, bb.x, bb.y);
          mma8(accL, al.x,al.y,al.z,al.w, bb.x, bb.y);
        }
      }
    }

    // epilogue: h_new = tanh((accH+accL) + pre + Ub)
    float2 o0, o1;
    o0.x = tanhf(accH[0] + accL[0] + pv0 + ub0);
    o0.y = tanhf(accH[1] + accL[1] + pv1 + ub1);
    o1.x = tanhf(accH[2] + accL[2] + pv2 + ub0);
    o1.y = tanhf(accH[3] + accL[3] + pv3 + ub1);
    *(float2*)&hnew[(size_t)mr*HH + nc]     = o0;
    *(float2*)&hnew[(size_t)(mr+8)*HH + nc] = o1;

    // monotonic global barrier across 128 CTAs (proven in round 4; keep verbatim)
    if (t < SS-1){
      __threadfence();
      __syncthreads();
      if (tid == 0){
        atomicAdd(&g_cnt, 1u);
        const unsigned target = (unsigned)(t+1) * NCTA;
        volatile unsigned* vc = &g_cnt;
        while (*vc < target) { }
      }
      __syncthreads();
      __threadfence();
    }
  }
}

__global__ void k_final(const float* __restrict__ Vw, const float* __restrict__ Vb, float* __restrict__ out){
  int b = blockIdx.x;
  const float* h = g_h[0] + (size_t)b*HH;   // after 512 steps, result sits in g_h[0]
  float s = 0.f;
  for (int k = threadIdx.x; k < HH; k += 128) s += h[k]*Vw[k];
  #pragma unroll
  for (int o=16;o;o>>=1) s += __shfl_down_sync(0xffffffffu, s, o);
  __shared__ float red[4];
  if ((threadIdx.x & 31) == 0) red[threadIdx.x>>5] = s;
  __syncthreads();
  if (threadIdx.x == 0){
    float tot = red[0]+red[1]+red[2]+red[3] + Vb[0];
    out[b] = 1.f/(1.f + expf(-tot));
  }
}

extern "C" void kernel_launch(void* const* d_in, const int* in_sizes, int n_in,
                              void* d_out, int out_size){
  (void)in_sizes; (void)n_in; (void)out_size;
  const int*   x   = (const int*)d_in[0];
  const float* emb = (const float*)d_in[1];
  const float* Ww  = (const float*)d_in[2];
  const float* Wb  = (const float*)d_in[3];
  const float* Uw  = (const float*)d_in[4];
  const float* Ubv = (const float*)d_in[5];
  const float* Vw  = (const float*)d_in[6];
  const float* Vb  = (const float*)d_in[7];
  float* out = (float*)d_out;

  static bool attr_done = false;
  if (!attr_done){
    cudaFuncSetAttribute(k_scan, cudaFuncAttributeMaxDynamicSharedMemorySize, SMEM_WORDS*4);
    attr_done = true;
  }

  k_init<<<(BB*HH+255)/256, 256>>>();
  k_pre<<<dim3(HH/64, TOK/64), 256>>>(x, emb, Ww, Wb);
  k_scan<<<dim3(32, 4), 256, SMEM_WORDS*4>>>(Uw, Ubv);
  k_final<<<BB, 128>>>(Vw, Vb, out);
}

// round 6
// speedup vs baseline: 1.6422x; 1.6422x over previous
#include <cuda_runtime.h>
#include <cstdint>

#define BB 128
#define SS 512
#define EE 512
#define HH 1024
#define TOK (BB*SS)
#define NCTA 256

// Scratch (allocation-free rule: __device__ globals)
__device__ float g_pre[(size_t)TOK * HH];   // [s*B + b][h], fp32
__device__ float g_h[2][BB * HH];           // ping-pong hidden state
__device__ unsigned g_cnt;                  // monotonic barrier counter

__device__ __forceinline__ unsigned f2tf(float f){
  unsigned u; asm("cvt.rna.tf32.f32 %0, %1;" : "=r"(u) : "f"(f)); return u;
}

__device__ __forceinline__ void mma8(float c[4], unsigned a0,unsigned a1,unsigned a2,unsigned a3,
                                     unsigned b0,unsigned b1){
  asm volatile("mma.sync.aligned.m16n8k8.row.col.f32.tf32.tf32.f32 "
    "{%0,%1,%2,%3}, {%4,%5,%6,%7}, {%8,%9}, {%0,%1,%2,%3};"
    : "+f"(c[0]),"+f"(c[1]),"+f"(c[2]),"+f"(c[3])
    : "r"(a0),"r"(a1),"r"(a2),"r"(a3),"r"(b0),"r"(b1));
}

__global__ void k_init(){
  int i = blockIdx.x*blockDim.x + threadIdx.x;
  if (i < BB*HH) g_h[0][i] = 0.f;
  if (i == 0){ g_cnt = 0u; }
}

// pre[s*B+b][h] = dot(emb[x[b][s]], W[h]) + Wb[h]   (M=65536, N=1024, K=512)
__global__ __launch_bounds__(256) void k_pre(const int* __restrict__ x, const float* __restrict__ emb,
                                             const float* __restrict__ Ww, const float* __restrict__ Wb){
  __shared__ unsigned As[64][33];
  __shared__ unsigned Bsm[64][33];
  __shared__ const float* rowp[64];
  const int tid = threadIdx.x;
  const int m0 = blockIdx.y*64, n0 = blockIdx.x*64;
  if (tid < 64){
    int tok = m0 + tid;
    int b = tok & (BB-1), s = tok >> 7;
    rowp[tid] = emb + (size_t)x[b*SS + s]*EE;
  }
  __syncthreads();
  const int lane = tid & 31, wid = tid >> 5;
  const int wm = wid >> 1, wn = wid & 1;
  const int gr = lane >> 2, gq = lane & 3;
  float acc[4][4];
  #pragma unroll
  for (int i=0;i<4;i++){ acc[i][0]=0.f; acc[i][1]=0.f; acc[i][2]=0.f; acc[i][3]=0.f; }

  for (int kt = 0; kt < EE/32; ++kt){
    const int k0 = kt*32;
    #pragma unroll
    for (int it=0; it<2; ++it){
      int id = tid + it*256;
      int r = id >> 3, c4 = (id & 7)*4;
      float4 v = *(const float4*)(rowp[r] + k0 + c4);
      As[r][c4+0]=f2tf(v.x); As[r][c4+1]=f2tf(v.y); As[r][c4+2]=f2tf(v.z); As[r][c4+3]=f2tf(v.w);
      float4 w = *(const float4*)(Ww + (size_t)(n0+r)*EE + k0 + c4);
      Bsm[r][c4+0]=f2tf(w.x); Bsm[r][c4+1]=f2tf(w.y); Bsm[r][c4+2]=f2tf(w.z); Bsm[r][c4+3]=f2tf(w.w);
    }
    __syncthreads();
    #pragma unroll
    for (int kk=0; kk<4; ++kk){
      unsigned a0 = As[wm*16+gr  ][kk*8+gq];
      unsigned a1 = As[wm*16+gr+8][kk*8+gq];
      unsigned a2 = As[wm*16+gr  ][kk*8+gq+4];
      unsigned a3 = As[wm*16+gr+8][kk*8+gq+4];
      #pragma unroll
      for (int nf=0; nf<4; ++nf){
        int nr = wn*32 + nf*8 + gr;
        mma8(acc[nf], a0,a1,a2,a3, Bsm[nr][kk*8+gq], Bsm[nr][kk*8+gq+4]);
      }
    }
    __syncthreads();
  }
  #pragma unroll
  for (int nf=0; nf<4; ++nf){
    int nc = n0 + wn*32 + nf*8 + 2*gq;
    int mr = m0 + wm*16 + gr;
    float wb0 = Wb[nc], wb1 = Wb[nc+1];
    g_pre[(size_t)mr*HH + nc]        = acc[nf][0] + wb0;
    g_pre[(size_t)mr*HH + nc + 1]    = acc[nf][1] + wb1;
    g_pre[(size_t)(mr+8)*HH + nc]    = acc[nf][2] + wb0;
    g_pre[(size_t)(mr+8)*HH + nc+1]  = acc[nf][3] + wb1;
  }
}

// ---------------- persistent recurrence kernel ----------------
// 256 CTAs = 4 (M, 32 rows) x 64 (N, 16 cols), 2 CTAs/SM, 256 threads, 8 warps.
// Warp (wm, wn, wks): wm=wid&1 (m-half), wn=(wid>>1)&1 (n-block of 8), wks=wid>>2
// (k-half of each chunk). Warp tile 16x8, inline hi/lo cvt (round-4 proven path).
// Pairwise k-half reduction in SMEM at epilogue.
// SMEM words: Bp [0,16384) packed U (16 cols); stage [16384, 16384+2*4224).
#define SM_BP    0
#define SM_STAGE 16384
#define STAGE_WORDS (32*132)
#define SMEM_WORDS (16384 + 2*STAGE_WORDS)

__device__ __forceinline__ void cpa16(unsigned* dst_sm, const float* src){
  uint32_t sa = (uint32_t)__cvta_generic_to_shared(dst_sm);
  asm volatile("cp.async.cg.shared.global [%0], [%1], 16;" :: "r"(sa), "l"(src));
}

__global__ __launch_bounds__(256, 2) void k_scan(const float* __restrict__ U, const float* __restrict__ Ub){
  extern __shared__ unsigned smw[];
  const int tid = threadIdx.x, lane = tid & 31, wid = tid >> 5;
  const int gr = lane >> 2, gq = lane & 3;
  const int wm = wid & 1, wn = (wid >> 1) & 1, wks = wid >> 2;
  const int m0 = blockIdx.y*32, n0 = blockIdx.x*16;

  // ---- pack U slice (rows n0..n0+15 of U, full K) into tf32 B-fragments ----
  // (n,k) -> word ((g*2 + (n>>3))*32 + (n&7)*4 + (kk&3))*2 + (kk>>2); g=k>>3, kk=k&7
  for (int e = tid; e < 16*HH; e += 256){
    int n = e >> 10, k = e & (HH-1);
    float v = U[(size_t)(n0+n)*HH + k];
    int g = k >> 3, kk = k & 7;
    int w = ((g*2 + (n>>3))*32 + (n&7)*4 + (kk&3))*2 + (kk>>2);
    smw[SM_BP + w] = f2tf(v);
  }
  const int nc = n0 + wn*8 + 2*gq;
  const int mr = m0 + wm*16 + gr;
  const float ub0 = Ub[nc], ub1 = Ub[nc+1];
  __syncthreads();

  for (int t = 0; t < SS; ++t){
    const float* __restrict__ hold = g_h[t & 1];
    float* __restrict__ hnew = g_h[(t & 1) ^ 1];
    const float* __restrict__ pre = g_pre + (size_t)t*BB*HH;

    float pv0, pv1, pv2, pv3;
    if (wks == 0){
      pv0 = pre[(size_t)mr*HH + nc];
      pv1 = pre[(size_t)mr*HH + nc + 1];
      pv2 = pre[(size_t)(mr+8)*HH + nc];
      pv3 = pre[(size_t)(mr+8)*HH + nc + 1];
    }
    float accH[4] = {0.f,0.f,0.f,0.f};
    float accL[4] = {0.f,0.f,0.f,0.f};

    // prefetch chunk 0 (32 rows x 128 floats) into stage buf 0
    #pragma unroll
    for (int i=0;i<4;++i){
      int idx = tid + i*256; int r = idx >> 5, j = idx & 31;
      cpa16(smw + SM_STAGE + r*132 + j*4, hold + (size_t)(m0+r)*HH + j*4);
    }
    asm volatile("cp.async.commit_group;");

    #pragma unroll 1
    for (int c = 0; c < 8; ++c){
      if (c < 7){
        int buf = (c+1) & 1;
        #pragma unroll
        for (int i=0;i<4;++i){
          int idx = tid + i*256; int r = idx >> 5, j = idx & 31;
          cpa16(smw + SM_STAGE + buf*STAGE_WORDS + r*132 + j*4,
                hold + (size_t)(m0+r)*HH + (c+1)*128 + j*4);
        }
        asm volatile("cp.async.commit_group;");
        asm volatile("cp.async.wait_group 1;" ::: "memory");
      } else {
        asm volatile("cp.async.wait_group 0;" ::: "memory");
      }
      __syncthreads();   // stage[c&1] ready for all warps

      // inline hi/lo cvt + mma over this warp's k-half of the chunk (8 kb groups)
      const float* st = (const float*)(smw + SM_STAGE + (c&1)*STAGE_WORDS)
                        + (wm*16+gr)*132 + wks*64 + gq;
      const unsigned* bp = smw + SM_BP + ((c*16 + wks*8)*2 + wn)*64 + lane*2;
      #pragma unroll
      for (int kb = 0; kb < 8; ++kb){
        float v0 = st[kb*8];
        float v1 = st[kb*8 + 8*132];
        float v2 = st[kb*8 + 4];
        float v3 = st[kb*8 + 4 + 8*132];
        unsigned h0=f2tf(v0), h1=f2tf(v1), h2=f2tf(v2), h3=f2tf(v3);
        unsigned l0=f2tf(v0-__uint_as_float(h0));
        unsigned l1=f2tf(v1-__uint_as_float(h1));
        unsigned l2=f2tf(v2-__uint_as_float(h2));
        unsigned l3=f2tf(v3-__uint_as_float(h3));
        uint2 bb = *(const uint2*)(bp + kb*128);
        mma8(accH, h0,h1,h2,h3, bb.x, bb.y);
        mma8(accL, l0,l1,l2,l3, bb.x, bb.y);
      }
      __syncthreads();   // all warps done with stage[c&1] before refill
    }

    // ---- pairwise k-half reduction via SMEM (stage area is free now) ----
    float r0 = accH[0]+accL[0], r1 = accH[1]+accL[1];
    float r2 = accH[2]+accL[2], r3 = accH[3]+accL[3];
    if (wks == 1){
      float* red = (float*)(smw + SM_STAGE) + (((wm*2+wn)*32 + lane)*4);
      red[0]=r0; red[1]=r1; red[2]=r2; red[3]=r3;
    }
    __syncthreads();
    if (wks == 0){
      const float4 p = *(const float4*)((const float*)(smw + SM_STAGE) + (((wm*2+wn)*32 + lane)*4));
      float2 o0, o1;
      o0.x = tanhf(r0 + p.x + pv0 + ub0);
      o0.y = tanhf(r1 + p.y + pv1 + ub1);
      o1.x = tanhf(r2 + p.z + pv2 + ub0);
      o1.y = tanhf(r3 + p.w + pv3 + ub1);
      *(float2*)&hnew[(size_t)mr*HH + nc]     = o0;
      *(float2*)&hnew[(size_t)(mr+8)*HH + nc] = o1;
    }

    // monotonic global barrier across 256 CTAs (proven pattern; count scaled)
    if (t < SS-1){
      __threadfence();
      __syncthreads();
      if (tid == 0){
        atomicAdd(&g_cnt, 1u);
        const unsigned target = (unsigned)(t+1) * NCTA;
        volatile unsigned* vc = &g_cnt;
        while (*vc < target) { }
      }
      __syncthreads();
      __threadfence();
    }
  }
}

__global__ void k_final(const float* __restrict__ Vw, const float* __restrict__ Vb, float* __restrict__ out){
  int b = blockIdx.x;
  const float* h = g_h[0] + (size_t)b*HH;   // after 512 steps, result sits in g_h[0]
  float s = 0.f;
  for (int k = threadIdx.x; k < HH; k += 128) s += h[k]*Vw[k];
  #pragma unroll
  for (int o=16;o;o>>=1) s += __shfl_down_sync(0xffffffffu, s, o);
  __shared__ float red[4];
  if ((threadIdx.x & 31) == 0) red[threadIdx.x>>5] = s;
  __syncthreads();
  if (threadIdx.x == 0){
    float tot = red[0]+red[1]+red[2]+red[3] + Vb[0];
    out[b] = 1.f/(1.f + expf(-tot));
  }
}

extern "C" void kernel_launch(void* const* d_in, const int* in_sizes, int n_in,
                              void* d_out, int out_size){
  (void)in_sizes; (void)n_in; (void)out_size;
  const int*   x   = (const int*)d_in[0];
  const float* emb = (const float*)d_in[1];
  const float* Ww  = (const float*)d_in[2];
  const float* Wb  = (const float*)d_in[3];
  const float* Uw  = (const float*)d_in[4];
  const float* Ubv = (const float*)d_in[5];
  const float* Vw  = (const float*)d_in[6];
  const float* Vb  = (const float*)d_in[7];
  float* out = (float*)d_out;

  static bool attr_done = false;
  if (!attr_done){
    cudaFuncSetAttribute(k_scan, cudaFuncAttributeMaxDynamicSharedMemorySize, SMEM_WORDS*4);
    attr_done = true;
  }

  k_init<<<(BB*HH+255)/256, 256>>>();
  k_pre<<<dim3(HH/64, TOK/64), 256>>>(x, emb, Ww, Wb);
  k_scan<<<dim3(64, 4), 256, SMEM_WORDS*4>>>(Uw, Ubv);
  k_final<<<BB, 128>>>(Vw, Vb, out);
}